// round 1
// baseline (speedup 1.0000x reference)
#include <cuda_runtime.h>

// Single-layer LSTM, T=4096, B=1024, I=H=4, seq-first, zero init state.
// Parallelization: 4 lanes per batch element (lane owns hidden unit j and the
// 4 gate rows {i,f,g,o} for that unit). 4096 threads = 128 warps, spread as
// 128 blocks x 32 threads -> 1 warp per SM (full SMSP issue/MUFU rate per warp).
// Recurrence is serial in T; runtime = T * per-step critical path (~125 cyc).
//
// Activation trick: sigmoid(x) = 1/(1 + 2^(-log2e * x)); the -log2e (or
// -2*log2e for tanh rows) is pre-folded into the weights/bias at load time so
// no scaling multiply is on the critical path. ex2.approx + rcp.approx give
// ~1e-6 error (well under the 1e-3 gate).

#define TLEN   4096
#define BATCH  1024
#define OUTSTRIDE (BATCH * 4)
#define UNROLL 8

__device__ __forceinline__ float ex2f(float x) {
    float y; asm("ex2.approx.ftz.f32 %0, %1;" : "=f"(y) : "f"(x)); return y;
}
__device__ __forceinline__ float rcpf(float x) {
    float y; asm("rcp.approx.ftz.f32 %0, %1;" : "=f"(y) : "f"(x)); return y;
}

__global__ void __launch_bounds__(32, 1)
lstm_recur(const float* __restrict__ input,
           const float* __restrict__ W_ih,
           const float* __restrict__ W_hh,
           const float* __restrict__ b_ih,
           const float* __restrict__ b_hh,
           float* __restrict__ out)
{
    const int g = blockIdx.x * 32 + threadIdx.x;   // 0..4095
    const int b = g >> 2;                          // batch element
    const int j = g & 3;                           // hidden unit owned by lane

    const float NL2E = -1.4426950408889634f;       // -log2(e)

    // Per-lane weight registers. Gate q: 0=i, 1=f, 2=g(tanh), 3=o.
    // Row r = q*4 + j of the [16, 4] weight matrices.
    // whh is xor-permuted so that the value obtained from shfl_xor(h, m)
    // multiplies whh[q][m] (compile-time register index -> no spills).
    float wih[4][4], whh[4][4], bias[4];
#pragma unroll
    for (int q = 0; q < 4; ++q) {
        const int r = q * 4 + j;
        const float s = (q == 2) ? (2.0f * NL2E) : NL2E;  // tanh row gets -2*log2e
#pragma unroll
        for (int m = 0; m < 4; ++m) {
            wih[q][m] = W_ih[r * 4 + m] * s;
            whh[q][m] = W_hh[r * 4 + (j ^ m)] * s;
        }
        bias[q] = (b_ih[r] + b_hh[r]) * s;
    }

    // x_t for this batch element is a contiguous float4 (I=4).
    const float4* __restrict__ xin = reinterpret_cast<const float4*>(input) + b;

    // 8-deep software prefetch (double buffer): ~1000 cyc cover > 577 DRAM lat.
    float4 xbuf[UNROLL], xnxt[UNROLL];
#pragma unroll
    for (int u = 0; u < UNROLL; ++u) xbuf[u] = xin[u * BATCH];

    float h = 0.0f, c = 0.0f;
    float* op = out + g;

    for (int t0 = 0; t0 < TLEN; t0 += UNROLL) {
        // Prefetch next block (clamped tail load; harmless redundant read).
#pragma unroll
        for (int u = 0; u < UNROLL; ++u) {
            int tp = t0 + UNROLL + u;
            tp = (tp < TLEN) ? tp : (TLEN - 1);
            xnxt[u] = xin[tp * BATCH];
        }

#pragma unroll
        for (int u = 0; u < UNROLL; ++u) {
            const float x0 = xbuf[u].x, x1 = xbuf[u].y,
                        x2 = xbuf[u].z, x3 = xbuf[u].w;

            // Input projection (off the serial critical path: x is prefetched).
            float acc[4];
#pragma unroll
            for (int q = 0; q < 4; ++q) {
                float a  = fmaf(x0, wih[q][0], bias[q]);
                float b2 = x1 * wih[q][1];
                a  = fmaf(x2, wih[q][2], a);
                b2 = fmaf(x3, wih[q][3], b2);
                acc[q] = a + b2;
            }

            // Exchange hidden state within the 4-lane group (3 parallel shfls,
            // overlapped with the self-h FMA below).
            const float h1 = __shfl_xor_sync(0xffffffffu, h, 1);
            const float h2 = __shfl_xor_sync(0xffffffffu, h, 2);
            const float h3 = __shfl_xor_sync(0xffffffffu, h, 3);

#pragma unroll
            for (int q = 0; q < 4; ++q) {
                float a  = fmaf(h,  whh[q][0], acc[q]);   // starts before shfls land
                float b2 = h1 * whh[q][1];
                a  = fmaf(h2, whh[q][2], a);
                b2 = fmaf(h3, whh[q][3], b2);
                acc[q] = a + b2;
            }

            // acc already pre-scaled: sigmoid = rcp(1 + ex2(acc)),
            // tanh = 2*rcp(1 + ex2(acc)) - 1.
            const float si = rcpf(1.0f + ex2f(acc[0]));
            const float sf = rcpf(1.0f + ex2f(acc[1]));
            const float tg = fmaf(rcpf(1.0f + ex2f(acc[2])), 2.0f, -1.0f);
            const float so = rcpf(1.0f + ex2f(acc[3]));

            c = fmaf(si, tg, sf * c);
            const float tc = fmaf(rcpf(1.0f + ex2f(c * (2.0f * NL2E))), 2.0f, -1.0f);
            h = so * tc;

            // out[(t, b, j)] -> 32 consecutive floats per warp (coalesced).
            op[(t0 + u) * OUTSTRIDE] = h;
        }

#pragma unroll
        for (int u = 0; u < UNROLL; ++u) xbuf[u] = xnxt[u];
    }
}

extern "C" void kernel_launch(void* const* d_in, const int* in_sizes, int n_in,
                              void* d_out, int out_size)
{
    const float* input = (const float*)d_in[0];
    const float* W_ih  = (const float*)d_in[1];
    const float* W_hh  = (const float*)d_in[2];
    const float* b_ih  = (const float*)d_in[3];
    const float* b_hh  = (const float*)d_in[4];
    float* out = (float*)d_out;

    // 4096 lanes = B(1024) * H(4); 128 blocks x 32 -> one warp per SM.
    lstm_recur<<<128, 32>>>(input, W_ih, W_hh, b_ih, b_hh, out);
}

// round 2
// speedup vs baseline: 1.6746x; 1.6746x over previous
#include <cuda_runtime.h>

// Single-layer LSTM, T=4096, B=1024, I=H=4, seq-first, zero init state.
// 4 lanes per batch element; 128 blocks x 32 threads -> 1 warp per SM.
//
// R2 change: activations via hardware MUFU.TANH (tanh.approx.f32).
//   sigmoid(x) = 0.5 + 0.5*tanh(x/2), with the 0.5 pre-folded into the
//   weights/bias of the i,f,o rows so the halving is free.
//   tanh rows (g, and tanh(c)) use MUFU.TANH directly.
// This cuts the per-step MUFU count 10 -> 5 (pipe floor 80 -> 40 cyc)
// and the serial chain ~134 -> ~86 cyc.

#define TLEN   4096
#define BATCH  1024
#define OUTSTRIDE (BATCH * 4)
#define UNROLL 8

__device__ __forceinline__ float tanhf_a(float x) {
    float y; asm("tanh.approx.f32 %0, %1;" : "=f"(y) : "f"(x)); return y;
}
__device__ __forceinline__ float shfl_bfly(float v, int m) {
    float y;
    asm volatile("shfl.sync.bfly.b32 %0, %1, %2, 0x1f, 0xffffffff;"
                 : "=f"(y) : "f"(v), "r"(m));
    return y;
}

__global__ void __launch_bounds__(32, 1)
lstm_recur(const float* __restrict__ input,
           const float* __restrict__ W_ih,
           const float* __restrict__ W_hh,
           const float* __restrict__ b_ih,
           const float* __restrict__ b_hh,
           float* __restrict__ out)
{
    const int g = blockIdx.x * 32 + threadIdx.x;   // 0..4095
    const int b = g >> 2;                          // batch element
    const int j = g & 3;                           // hidden unit owned by lane

    // Gate q: 0=i, 1=f, 2=g(tanh), 3=o. Row r = q*4 + j of the [16,4] mats.
    // Sigmoid rows (q != 2) are pre-scaled by 0.5: sigmoid(x)=0.5+0.5*tanh(x/2).
    // whh xor-permuted: shfl_xor(h, m) multiplies whh[q][m].
    float wih[4][4], whh[4][4], bias[4];
#pragma unroll
    for (int q = 0; q < 4; ++q) {
        const int r = q * 4 + j;
        const float s = (q == 2) ? 1.0f : 0.5f;
#pragma unroll
        for (int m = 0; m < 4; ++m) {
            wih[q][m] = W_ih[r * 4 + m] * s;
            whh[q][m] = W_hh[r * 4 + (j ^ m)] * s;
        }
        bias[q] = (b_ih[r] + b_hh[r]) * s;
    }

    const float4* __restrict__ xin = reinterpret_cast<const float4*>(input) + b;

    // 8-deep software prefetch (double buffer): ~700+ cyc cover > 577 DRAM lat.
    float4 xbuf[UNROLL], xnxt[UNROLL];
#pragma unroll
    for (int u = 0; u < UNROLL; ++u) xbuf[u] = xin[u * BATCH];

    float h = 0.0f, c = 0.0f;
    float* op = out + g;

    for (int t0 = 0; t0 < TLEN; t0 += UNROLL) {
#pragma unroll
        for (int u = 0; u < UNROLL; ++u) {
            int tp = t0 + UNROLL + u;
            tp = (tp < TLEN) ? tp : (TLEN - 1);
            xnxt[u] = xin[tp * BATCH];
        }

#pragma unroll
        for (int u = 0; u < UNROLL; ++u) {
            const float x0 = xbuf[u].x, x1 = xbuf[u].y,
                        x2 = xbuf[u].z, x3 = xbuf[u].w;

            // Input projection (off the serial critical path).
            float acc[4];
#pragma unroll
            for (int q = 0; q < 4; ++q) {
                float a  = fmaf(x0, wih[q][0], bias[q]);
                float b2 = x1 * wih[q][1];
                a  = fmaf(x2, wih[q][2], a);
                b2 = fmaf(x3, wih[q][3], b2);
                acc[q] = a + b2;
            }

            // Exchange hidden state within the 4-lane group.
            const float h1 = shfl_bfly(h, 1);
            const float h2 = shfl_bfly(h, 2);
            const float h3 = shfl_bfly(h, 3);

#pragma unroll
            for (int q = 0; q < 4; ++q) {
                float a  = fmaf(h,  whh[q][0], acc[q]);   // starts before shfls land
                float b2 = h1 * whh[q][1];
                a  = fmaf(h2, whh[q][2], a);
                b2 = fmaf(h3, whh[q][3], b2);
                acc[q] = a + b2;
            }

            // Activations via MUFU.TANH. Sigmoid rows were pre-halved.
            const float si = fmaf(tanhf_a(acc[0]), 0.5f, 0.5f);
            const float sf = fmaf(tanhf_a(acc[1]), 0.5f, 0.5f);
            const float tg = tanhf_a(acc[2]);
            const float so = fmaf(tanhf_a(acc[3]), 0.5f, 0.5f);

            c = fmaf(si, tg, sf * c);
            h = so * tanhf_a(c);

            op[(t0 + u) * OUTSTRIDE] = h;   // coalesced: 32 consecutive floats
        }

#pragma unroll
        for (int u = 0; u < UNROLL; ++u) xbuf[u] = xnxt[u];
    }
}

extern "C" void kernel_launch(void* const* d_in, const int* in_sizes, int n_in,
                              void* d_out, int out_size)
{
    const float* input = (const float*)d_in[0];
    const float* W_ih  = (const float*)d_in[1];
    const float* W_hh  = (const float*)d_in[2];
    const float* b_ih  = (const float*)d_in[3];
    const float* b_hh  = (const float*)d_in[4];
    float* out = (float*)d_out;

    lstm_recur<<<128, 32>>>(input, W_ih, W_hh, b_ih, b_hh, out);
}